// round 14
// baseline (speedup 1.0000x reference)
#include <cuda_runtime.h>
#include <cuda_bf16.h>
#include <cstdint>

#define NN 50000
#define NE 800000
#define F  128
#define NG 100

// ---- scratch (static __device__ globals; no allocation anywhere) ----
__device__ __align__(16) float g_deg[NN];
__device__ __align__(16) float g_dinv[NN];
__device__ __align__(16) uint32_t g_hb[NN * 64];    // XW product, bf16x2 (128 bf16/row)
__device__ __align__(16) uint32_t g_actb[NN * 64];  // relu activations, bf16x2
__device__ __align__(16) float g_pool[NG * F];
__device__ __align__(16) float g_cnt[NG];
__device__ int   g_cnt_in[NN];
__device__ int   g_ptr[NN + 1];
__device__ int   g_cur[NN];
__device__ __align__(16) int   g_csr_row[NE];
__device__ __align__(16) float g_csr_norm[NE];

// packed f32x2 helpers (B300 FFMA2 — only reachable via PTX)
#define FMA2(d, a, b) \
    asm("fma.rn.f32x2 %0, %1, %2, %0;" : "+l"(d) : "l"(a), "l"(b))
#define PACK2(out, lo, hi) \
    asm("mov.b64 %0, {%1, %2};" : "=l"(out) : "f"(lo), "f"(hi))
#define UNPACK2(lo, hi, in) \
    asm("mov.b64 {%0, %1}, %2;" : "=f"(lo), "=f"(hi) : "l"(in))
// d = bf16x2 with lo=a, hi=b
#define CVT_BF2(d, a, b) \
    asm("cvt.rn.bf16x2.f32 %0, %1, %2;" : "=r"(d) : "f"(b), "f"(a))

__device__ __forceinline__ float2 bf2f(uint32_t u) {
    return __bfloat1622float2(*reinterpret_cast<__nv_bfloat162*>(&u));
}

// ================= CSR build =================
__global__ void zero_misc_kernel() {
    int i = blockIdx.x * blockDim.x + threadIdx.x;
    if (i < NN) { g_deg[i] = 0.f; g_cnt_in[i] = 0; }
    if (i < NG * F) g_pool[i] = 0.f;
    if (i < NG) g_cnt[i] = 0.f;
}

__global__ void deg_count_kernel(const int* __restrict__ ei,
                                 const float* __restrict__ ew) {
    int t = blockIdx.x * blockDim.x + threadIdx.x;
    int e = t * 2;
    if (e < NE) {
        int2   c2 = *reinterpret_cast<const int2*>(&ei[NE + e]);
        float2 w2 = *reinterpret_cast<const float2*>(&ew[e]);
        atomicAdd(&g_deg[c2.x], w2.x);
        atomicAdd(&g_cnt_in[c2.x], 1);
        atomicAdd(&g_deg[c2.y], w2.y);
        atomicAdd(&g_cnt_in[c2.y], 1);
    }
}

__global__ void dinv_kernel(const int* __restrict__ batch) {
    int i = blockIdx.x * blockDim.x + threadIdx.x;
    if (i < NN) {
        g_dinv[i] = rsqrtf(g_deg[i] + 1.0f);
        int g = batch[i];
        if (g < 0) g = 0;
        if (g >= NG) g = NG - 1;
        atomicAdd(&g_cnt[g], 1.0f);
    }
}

// single-block exclusive scan over g_cnt_in -> g_ptr / g_cur (1024 thr x 49 items)
#define SCAN_T 1024
#define SCAN_I 49    // 1024*49 = 50176 >= NN
__global__ void __launch_bounds__(SCAN_T)
scan_kernel() {
    __shared__ int ts[SCAN_T];
    int t = threadIdx.x;
    int base = t * SCAN_I;

    int run = 0;
#pragma unroll 7
    for (int i = 0; i < SCAN_I; i++) {
        int idx = base + i;
        if (idx < NN) run += g_cnt_in[idx];
    }
    ts[t] = run;
    __syncthreads();
#pragma unroll
    for (int off = 1; off < SCAN_T; off <<= 1) {
        int v = (t >= off) ? ts[t - off] : 0;
        __syncthreads();
        ts[t] += v;
        __syncthreads();
    }
    int pre = (t > 0) ? ts[t - 1] : 0;   // exclusive prefix of this thread's range

    run = pre;
#pragma unroll 7
    for (int i = 0; i < SCAN_I; i++) {
        int idx = base + i;
        if (idx < NN) {
            int v = g_cnt_in[idx];       // L1/L2-hot reload
            g_cur[idx] = run;
            g_ptr[idx + 1] = run + v;
            run += v;
        }
    }
    if (t == 0) g_ptr[0] = 0;
}

__global__ void fill_kernel(const int* __restrict__ ei,
                            const float* __restrict__ ew) {
    int e = blockIdx.x * blockDim.x + threadIdx.x;
    if (e < NE) {
        int r = ei[e];
        int c = ei[NE + e];
        int pos = atomicAdd(&g_cur[c], 1);
        g_csr_row[pos] = r;
        g_csr_norm[pos] = g_dinv[r] * ew[e] * g_dinv[c];
    }
}

// ================= W-resident pipelined FFMA2 GEMM -> bf16 table =================
// USE_ACT=0: X from fp32 Xext. USE_ACT=1: X from bf16 g_actb.
#define WPAD 136
#define SM_W_FLOATS (128 * WPAD)
#define SM_X_FLOATS (2 * 16 * WPAD)
#define SM_GEMM_BYTES ((SM_W_FLOATS + SM_X_FLOATS) * 4)  // 87040

template <int USE_ACT>
__global__ void __launch_bounds__(256, 2)
gemm128_kernel(const float* __restrict__ Xext, const float* __restrict__ W, int n) {
    extern __shared__ __align__(16) float sm[];
    float* Wsm = sm;                    // [128][WPAD]
    float* Xsm = sm + SM_W_FLOATS;      // [2][16][WPAD]

    int tid = threadIdx.x;
    int cx = tid & 15;
    int ry = tid >> 4;
    int row0 = blockIdx.x * 128;

    int lr   = tid >> 1;
    int half = tid & 1;
    int kb   = half * 8;

    int xrow = row0 + lr;
    bool ok = xrow < n;
    int srow = ok ? xrow : 0;
    const float*    Xp  = Xext + (size_t)srow * 128 + kb;
    const uint32_t* Xbp = g_actb + (size_t)srow * 64 + kb / 2;
    const float*    Wp  = W + lr * 128 + kb;

#pragma unroll
    for (int kc = 0; kc < 8; kc++) {
        float4 w0 = *reinterpret_cast<const float4*>(Wp + kc * 16);
        float4 w1 = *reinterpret_cast<const float4*>(Wp + kc * 16 + 4);
        float* dst = Wsm + (kc * 16 + kb) * WPAD + lr;
        dst[0 * WPAD] = w0.x; dst[1 * WPAD] = w0.y;
        dst[2 * WPAD] = w0.z; dst[3 * WPAD] = w0.w;
        dst[4 * WPAD] = w1.x; dst[5 * WPAD] = w1.y;
        dst[6 * WPAD] = w1.z; dst[7 * WPAD] = w1.w;
    }

    // stage X chunk kc into buffer b
    auto stage_x = [&](int kc, int b, const float4& a0, const float4& a1,
                       const uint4& u) {
        float v[8];
        if (USE_ACT) {
            float2 f0 = bf2f(u.x), f1 = bf2f(u.y), f2 = bf2f(u.z), f3 = bf2f(u.w);
            v[0] = f0.x; v[1] = f0.y; v[2] = f1.x; v[3] = f1.y;
            v[4] = f2.x; v[5] = f2.y; v[6] = f3.x; v[7] = f3.y;
        } else {
            v[0] = a0.x; v[1] = a0.y; v[2] = a0.z; v[3] = a0.w;
            v[4] = a1.x; v[5] = a1.y; v[6] = a1.z; v[7] = a1.w;
        }
        float* dst = Xsm + (b * 16 + kb) * WPAD + lr;
#pragma unroll
        for (int j = 0; j < 8; j++) dst[j * WPAD] = ok ? v[j] : 0.f;
    };

    {
        float4 a0 = make_float4(0.f,0.f,0.f,0.f), a1 = a0;
        uint4 u = make_uint4(0,0,0,0);
        if (USE_ACT) u = *reinterpret_cast<const uint4*>(Xbp);
        else { a0 = *reinterpret_cast<const float4*>(Xp);
               a1 = *reinterpret_cast<const float4*>(Xp + 4); }
        stage_x(0, 0, a0, a1, u);
    }
    __syncthreads();

    uint64_t acc[8][4];
#pragma unroll
    for (int a = 0; a < 8; a++)
#pragma unroll
        for (int b = 0; b < 4; b++) acc[a][b] = 0ull;

    float4 px0, px1; uint4 pu;
#pragma unroll
    for (int kc = 0; kc < 8; kc++) {
        int buf = kc & 1;
        if (kc < 7) {   // prefetch next X chunk
            if (USE_ACT) pu = *reinterpret_cast<const uint4*>(Xbp + (kc + 1) * 8);
            else {
                px0 = *reinterpret_cast<const float4*>(Xp + (kc + 1) * 16);
                px1 = *reinterpret_cast<const float4*>(Xp + (kc + 1) * 16 + 4);
            }
        }

#pragma unroll
        for (int k = 0; k < 16; k++) {
            const float* wrow = Wsm + (kc * 16 + k) * WPAD;
            ulonglong2 wA = *reinterpret_cast<const ulonglong2*>(wrow + cx * 8);
            ulonglong2 wB = *reinterpret_cast<const ulonglong2*>(wrow + cx * 8 + 4);
            const float* xrowp = Xsm + (buf * 16 + k) * WPAD;
            float4 x0 = *reinterpret_cast<const float4*>(xrowp + ry * 8);
            float4 x1 = *reinterpret_cast<const float4*>(xrowp + ry * 8 + 4);
            float xr[8] = {x0.x, x0.y, x0.z, x0.w, x1.x, x1.y, x1.z, x1.w};
#pragma unroll
            for (int a = 0; a < 8; a++) {
                uint64_t xd;
                PACK2(xd, xr[a], xr[a]);
                FMA2(acc[a][0], xd, wA.x);
                FMA2(acc[a][1], xd, wA.y);
                FMA2(acc[a][2], xd, wB.x);
                FMA2(acc[a][3], xd, wB.y);
            }
        }
        if (kc < 7) {
            stage_x(kc + 1, buf ^ 1, px0, px1, pu);
            __syncthreads();
        }
    }

    // epilogue: f32x2 pairs -> bf16x2, 16B per row per thread
#pragma unroll
    for (int a = 0; a < 8; a++) {
        int r = row0 + ry * 8 + a;
        if (r < n) {
            uint4 o;
            float lo, hi;
            UNPACK2(lo, hi, acc[a][0]); CVT_BF2(o.x, lo, hi);
            UNPACK2(lo, hi, acc[a][1]); CVT_BF2(o.y, lo, hi);
            UNPACK2(lo, hi, acc[a][2]); CVT_BF2(o.z, lo, hi);
            UNPACK2(lo, hi, acc[a][3]); CVT_BF2(o.w, lo, hi);
            *reinterpret_cast<uint4*>(&g_hb[(size_t)r * 64 + cx * 4]) = o;
        }
    }
}

// ================= fused aggregate + relu; act-store OR pool =================
__global__ void gather_kernel(const float* __restrict__ bias,
                              const int* __restrict__ batch, int do_pool) {
    int w = (blockIdx.x * blockDim.x + threadIdx.x) >> 5;
    int lane = threadIdx.x & 31;
    if (w >= NN) return;

    const uint2* __restrict__ hb = reinterpret_cast<const uint2*>(g_hb);
    int start = g_ptr[w];
    int end   = g_ptr[w + 1];
    float di = g_dinv[w];
    float s = di * di;

    uint2 us = hb[(size_t)w * 32 + lane];
    float2 s0 = bf2f(us.x), s1 = bf2f(us.y);
    float4 bv = reinterpret_cast<const float4*>(bias)[lane];
    float4 acc;
    acc.x = s0.x * s + bv.x;
    acc.y = s0.y * s + bv.y;
    acc.z = s1.x * s + bv.z;
    acc.w = s1.y * s + bv.w;

    int e = start;
    for (; e + 8 <= end; e += 8) {
        int   ri[8];
        float ni[8];
#pragma unroll
        for (int j = 0; j < 8; j++) { ri[j] = g_csr_row[e + j]; ni[j] = g_csr_norm[e + j]; }
        uint2 v[8];
#pragma unroll
        for (int j = 0; j < 8; j++) v[j] = hb[(size_t)ri[j] * 32 + lane];
#pragma unroll
        for (int j = 0; j < 8; j++) {
            float2 p0 = bf2f(v[j].x), p1 = bf2f(v[j].y);
            acc.x += ni[j] * p0.x;
            acc.y += ni[j] * p0.y;
            acc.z += ni[j] * p1.x;
            acc.w += ni[j] * p1.y;
        }
    }
    if (e + 4 <= end) {
        int   r0 = g_csr_row[e],   r1 = g_csr_row[e+1];
        int   r2 = g_csr_row[e+2], r3 = g_csr_row[e+3];
        float n0 = g_csr_norm[e],   n1 = g_csr_norm[e+1];
        float n2 = g_csr_norm[e+2], n3 = g_csr_norm[e+3];
        uint2 v0 = hb[(size_t)r0 * 32 + lane];
        uint2 v1 = hb[(size_t)r1 * 32 + lane];
        uint2 v2 = hb[(size_t)r2 * 32 + lane];
        uint2 v3 = hb[(size_t)r3 * 32 + lane];
        float2 a0 = bf2f(v0.x), b0 = bf2f(v0.y);
        float2 a1 = bf2f(v1.x), b1 = bf2f(v1.y);
        float2 a2 = bf2f(v2.x), b2 = bf2f(v2.y);
        float2 a3 = bf2f(v3.x), b3 = bf2f(v3.y);
        acc.x += n0*a0.x + n1*a1.x + n2*a2.x + n3*a3.x;
        acc.y += n0*a0.y + n1*a1.y + n2*a2.y + n3*a3.y;
        acc.z += n0*b0.x + n1*b1.x + n2*b2.x + n3*b3.x;
        acc.w += n0*b0.y + n1*b1.y + n2*b2.y + n3*b3.y;
        e += 4;
    }
    for (; e < end; e++) {
        int   r0 = g_csr_row[e];
        float n0 = g_csr_norm[e];
        uint2 v0 = hb[(size_t)r0 * 32 + lane];
        float2 p0 = bf2f(v0.x), p1 = bf2f(v0.y);
        acc.x += n0*p0.x; acc.y += n0*p0.y;
        acc.z += n0*p1.x; acc.w += n0*p1.y;
    }

    acc.x = fmaxf(acc.x, 0.f); acc.y = fmaxf(acc.y, 0.f);
    acc.z = fmaxf(acc.z, 0.f); acc.w = fmaxf(acc.w, 0.f);

    if (do_pool) {
        // layer 2: activations feed only the mean-pool — no act store
        int g = batch[w];
        if (g < 0) g = 0;
        if (g >= NG) g = NG - 1;
        float* dst = &g_pool[g * F + lane * 4];
        atomicAdd(dst + 0, acc.x);
        atomicAdd(dst + 1, acc.y);
        atomicAdd(dst + 2, acc.z);
        atomicAdd(dst + 3, acc.w);
    } else {
        // layer 1: store bf16 activations for gemm2
        uint2 o;
        CVT_BF2(o.x, acc.x, acc.y);
        CVT_BF2(o.y, acc.z, acc.w);
        reinterpret_cast<uint2*>(g_actb)[(size_t)w * 32 + lane] = o;
    }
}

// ================= head MLP =================
__global__ void head_kernel(const float* __restrict__ l1w, const float* __restrict__ l1b,
                            const float* __restrict__ l2w, const float* __restrict__ l2b,
                            float* __restrict__ out) {
    int g = blockIdx.x;
    int t = threadIdx.x;
    __shared__ float gv[F];
    __shared__ float hv[F];
    __shared__ float red[F];

    float c = fmaxf(g_cnt[g], 1.0f);
    gv[t] = g_pool[g * F + t] / c;
    __syncthreads();

    float s = l1b[t];
    const float* wrow = l1w + t * F;
#pragma unroll 8
    for (int k = 0; k < F; k++) s += wrow[k] * gv[k];
    hv[t] = fmaxf(s, 0.f);
    __syncthreads();

    for (int o = 0; o < 2; o++) {
        red[t] = l2w[o * F + t] * hv[t];
        __syncthreads();
        for (int st = 64; st > 0; st >>= 1) {
            if (t < st) red[t] += red[t + st];
            __syncthreads();
        }
        if (t == 0) out[g * 2 + o] = red[0] + l2b[o];
        __syncthreads();
    }
}

extern "C" void kernel_launch(void* const* d_in, const int* in_sizes, int n_in,
                              void* d_out, int out_size) {
    const float* x     = (const float*)d_in[0];
    const int*   ei    = (const int*)d_in[1];
    const float* ew    = (const float*)d_in[2];
    const int*   batch = (const int*)d_in[3];
    const float* W1    = (const float*)d_in[4];
    const float* b1    = (const float*)d_in[5];
    const float* W2    = (const float*)d_in[6];
    const float* b2    = (const float*)d_in[7];
    const float* l1w   = (const float*)d_in[8];
    const float* l1b   = (const float*)d_in[9];
    const float* l2w   = (const float*)d_in[10];
    const float* l2b   = (const float*)d_in[11];
    float* out         = (float*)d_out;

    // lazily-created side stream + events (host objects only; no device memory)
    static cudaStream_t s2 = nullptr;
    static cudaEvent_t ev_fork = nullptr, ev_gemm = nullptr;
    static int smem_set = 0;
    if (s2 == nullptr) {
        cudaStreamCreateWithFlags(&s2, cudaStreamNonBlocking);
        cudaEventCreateWithFlags(&ev_fork, cudaEventDisableTiming);
        cudaEventCreateWithFlags(&ev_gemm, cudaEventDisableTiming);
    }
    if (!smem_set) {
        cudaFuncSetAttribute(gemm128_kernel<0>,
                             cudaFuncAttributeMaxDynamicSharedMemorySize, SM_GEMM_BYTES);
        cudaFuncSetAttribute(gemm128_kernel<1>,
                             cudaFuncAttributeMaxDynamicSharedMemorySize, SM_GEMM_BYTES);
        smem_set = 1;
    }

    const int T = 256;
    int gemm_blocks   = (NN + 127) / 128;
    int gather_blocks = (NN * 32 + T - 1) / T;

    // fork point: side stream joins the capture graph here
    cudaEventRecord(ev_fork, 0);
    cudaStreamWaitEvent(s2, ev_fork, 0);

    // branch A (main): CSR build
    zero_misc_kernel<<<(NN + T - 1) / T, T>>>();
    deg_count_kernel<<<(NE / 2 + T - 1) / T, T>>>(ei, ew);
    dinv_kernel<<<(NN + T - 1) / T, T>>>(batch);

    // branch B (s2): GEMM layer 1 (4th launch -> ncu window)
    gemm128_kernel<0><<<gemm_blocks, T, SM_GEMM_BYTES, s2>>>(x, W1, NN);
    cudaEventRecord(ev_gemm, s2);

    // branch A continued: single-kernel scan + fill
    scan_kernel<<<1, SCAN_T>>>();
    fill_kernel<<<(NE + T - 1) / T, T>>>(ei, ew);

    // join: gather1 needs CSR (A) AND g_hb from gemm1 (B)
    cudaStreamWaitEvent(0, ev_gemm, 0);
    gather_kernel<<<gather_blocks, T>>>(b1, batch, 0);

    // layer 2 (+ fused mean-pool accumulation, no act store)
    gemm128_kernel<1><<<gemm_blocks, T, SM_GEMM_BYTES>>>(x, W2, NN);
    gather_kernel<<<gather_blocks, T>>>(b2, batch, 1);

    // head
    head_kernel<<<NG, F>>>(l1w, l1b, l2w, l2b, out);
}

// round 15
// speedup vs baseline: 1.3110x; 1.3110x over previous
#include <cuda_runtime.h>
#include <cuda_bf16.h>
#include <cstdint>

#define NN 50000
#define NE 800000
#define F  128
#define NG 100
#define SCAN_B 1024
#define NSB ((NN + SCAN_B - 1) / SCAN_B)   // 49

// ---- scratch (static __device__ globals; no allocation anywhere) ----
__device__ __align__(16) float g_deg[NN];
__device__ __align__(16) float g_dinv[NN];
__device__ __align__(16) uint32_t g_hb[NN * 64];    // XW product, bf16x2 (128 bf16/row)
__device__ __align__(16) uint32_t g_actb[NN * 64];  // relu activations, bf16x2
__device__ __align__(16) float g_pool[NG * F];
__device__ __align__(16) float g_cnt[NG];
__device__ int   g_cnt_in[NN];
__device__ int   g_incl[NN];
__device__ int   g_bsum[NSB];
__device__ int   g_boff[NSB];
__device__ int   g_ptr[NN + 1];
__device__ int   g_cur[NN];
__device__ __align__(16) int   g_csr_row[NE];
__device__ __align__(16) float g_csr_norm[NE];

// packed f32x2 helpers (B300 FFMA2 — only reachable via PTX)
#define FMA2(d, a, b) \
    asm("fma.rn.f32x2 %0, %1, %2, %0;" : "+l"(d) : "l"(a), "l"(b))
#define PACK2(out, lo, hi) \
    asm("mov.b64 %0, {%1, %2};" : "=l"(out) : "f"(lo), "f"(hi))
#define UNPACK2(lo, hi, in) \
    asm("mov.b64 {%0, %1}, %2;" : "=f"(lo), "=f"(hi) : "l"(in))
// d = bf16x2 with lo=a, hi=b
#define CVT_BF2(d, a, b) \
    asm("cvt.rn.bf16x2.f32 %0, %1, %2;" : "=r"(d) : "f"(b), "f"(a))

__device__ __forceinline__ float2 bf2f(uint32_t u) {
    return __bfloat1622float2(*reinterpret_cast<__nv_bfloat162*>(&u));
}

// ================= CSR build =================
__global__ void zero_misc_kernel() {
    int i = blockIdx.x * blockDim.x + threadIdx.x;
    if (i < NN) { g_deg[i] = 0.f; g_cnt_in[i] = 0; }
    if (i < NG * F) g_pool[i] = 0.f;
    if (i < NG) g_cnt[i] = 0.f;
}

__global__ void deg_count_kernel(const int* __restrict__ ei,
                                 const float* __restrict__ ew) {
    int t = blockIdx.x * blockDim.x + threadIdx.x;
    int e = t * 2;
    if (e < NE) {
        int2   c2 = *reinterpret_cast<const int2*>(&ei[NE + e]);
        float2 w2 = *reinterpret_cast<const float2*>(&ew[e]);
        atomicAdd(&g_deg[c2.x], w2.x);
        atomicAdd(&g_cnt_in[c2.x], 1);
        atomicAdd(&g_deg[c2.y], w2.y);
        atomicAdd(&g_cnt_in[c2.y], 1);
    }
}

__global__ void dinv_kernel(const int* __restrict__ batch) {
    int i = blockIdx.x * blockDim.x + threadIdx.x;
    if (i < NN) {
        g_dinv[i] = rsqrtf(g_deg[i] + 1.0f);
        int g = batch[i];
        if (g < 0) g = 0;
        if (g >= NG) g = NG - 1;
        atomicAdd(&g_cnt[g], 1.0f);
    }
}

// 3-kernel parallel scan (R13 known-good): per-block inclusive, block offsets, combine
__global__ void scan1_kernel() {
    __shared__ int s[SCAN_B];
    int tid = threadIdx.x;
    int i = blockIdx.x * SCAN_B + tid;
    int v = (i < NN) ? g_cnt_in[i] : 0;
    s[tid] = v;
    __syncthreads();
#pragma unroll
    for (int off = 1; off < SCAN_B; off <<= 1) {
        int t = (tid >= off) ? s[tid - off] : 0;
        __syncthreads();
        s[tid] += t;
        __syncthreads();
    }
    if (i < NN) g_incl[i] = s[tid];
    if (tid == SCAN_B - 1) g_bsum[blockIdx.x] = s[tid];
}

__global__ void scan2_kernel() {
    if (threadIdx.x == 0) {
        int run = 0;
        for (int b = 0; b < NSB; b++) { g_boff[b] = run; run += g_bsum[b]; }
    }
}

__global__ void scan3_kernel() {
    int i = blockIdx.x * blockDim.x + threadIdx.x;
    if (i < NN) {
        int t = g_incl[i] + g_boff[i >> 10];
        g_ptr[i + 1] = t;
        g_cur[i] = t - g_cnt_in[i];
        if (i == 0) g_ptr[0] = 0;
    }
}

__global__ void fill_kernel(const int* __restrict__ ei,
                            const float* __restrict__ ew) {
    int e = blockIdx.x * blockDim.x + threadIdx.x;
    if (e < NE) {
        int r = ei[e];
        int c = ei[NE + e];
        int pos = atomicAdd(&g_cur[c], 1);
        g_csr_row[pos] = r;
        g_csr_norm[pos] = g_dinv[r] * ew[e] * g_dinv[c];
    }
}

// ================= W-resident pipelined FFMA2 GEMM -> bf16 table =================
// USE_ACT=0: X from fp32 Xext. USE_ACT=1: X from bf16 g_actb.
#define WPAD 136
#define SM_W_FLOATS (128 * WPAD)
#define SM_X_FLOATS (2 * 16 * WPAD)
#define SM_GEMM_BYTES ((SM_W_FLOATS + SM_X_FLOATS) * 4)  // 87040

template <int USE_ACT>
__global__ void __launch_bounds__(256, 2)
gemm128_kernel(const float* __restrict__ Xext, const float* __restrict__ W, int n) {
    extern __shared__ __align__(16) float sm[];
    float* Wsm = sm;                    // [128][WPAD]
    float* Xsm = sm + SM_W_FLOATS;      // [2][16][WPAD]

    int tid = threadIdx.x;
    int cx = tid & 15;
    int ry = tid >> 4;
    int row0 = blockIdx.x * 128;

    int lr   = tid >> 1;
    int half = tid & 1;
    int kb   = half * 8;

    int xrow = row0 + lr;
    bool ok = xrow < n;
    int srow = ok ? xrow : 0;
    const float*    Xp  = Xext + (size_t)srow * 128 + kb;
    const uint32_t* Xbp = g_actb + (size_t)srow * 64 + kb / 2;
    const float*    Wp  = W + lr * 128 + kb;

#pragma unroll
    for (int kc = 0; kc < 8; kc++) {
        float4 w0 = *reinterpret_cast<const float4*>(Wp + kc * 16);
        float4 w1 = *reinterpret_cast<const float4*>(Wp + kc * 16 + 4);
        float* dst = Wsm + (kc * 16 + kb) * WPAD + lr;
        dst[0 * WPAD] = w0.x; dst[1 * WPAD] = w0.y;
        dst[2 * WPAD] = w0.z; dst[3 * WPAD] = w0.w;
        dst[4 * WPAD] = w1.x; dst[5 * WPAD] = w1.y;
        dst[6 * WPAD] = w1.z; dst[7 * WPAD] = w1.w;
    }

    // stage X chunk into buffer b
    auto stage_x = [&](int b, const float4& a0, const float4& a1, const uint4& u) {
        float v[8];
        if (USE_ACT) {
            float2 f0 = bf2f(u.x), f1 = bf2f(u.y), f2 = bf2f(u.z), f3 = bf2f(u.w);
            v[0] = f0.x; v[1] = f0.y; v[2] = f1.x; v[3] = f1.y;
            v[4] = f2.x; v[5] = f2.y; v[6] = f3.x; v[7] = f3.y;
        } else {
            v[0] = a0.x; v[1] = a0.y; v[2] = a0.z; v[3] = a0.w;
            v[4] = a1.x; v[5] = a1.y; v[6] = a1.z; v[7] = a1.w;
        }
        float* dst = Xsm + (b * 16 + kb) * WPAD + lr;
#pragma unroll
        for (int j = 0; j < 8; j++) dst[j * WPAD] = ok ? v[j] : 0.f;
    };

    {
        float4 a0 = make_float4(0.f,0.f,0.f,0.f), a1 = a0;
        uint4 u = make_uint4(0,0,0,0);
        if (USE_ACT) u = *reinterpret_cast<const uint4*>(Xbp);
        else { a0 = *reinterpret_cast<const float4*>(Xp);
               a1 = *reinterpret_cast<const float4*>(Xp + 4); }
        stage_x(0, a0, a1, u);
    }
    __syncthreads();

    uint64_t acc[8][4];
#pragma unroll
    for (int a = 0; a < 8; a++)
#pragma unroll
        for (int b = 0; b < 4; b++) acc[a][b] = 0ull;

    float4 px0, px1; uint4 pu;
#pragma unroll
    for (int kc = 0; kc < 8; kc++) {
        int buf = kc & 1;
        if (kc < 7) {   // prefetch next X chunk
            if (USE_ACT) pu = *reinterpret_cast<const uint4*>(Xbp + (kc + 1) * 8);
            else {
                px0 = *reinterpret_cast<const float4*>(Xp + (kc + 1) * 16);
                px1 = *reinterpret_cast<const float4*>(Xp + (kc + 1) * 16 + 4);
            }
        }

#pragma unroll
        for (int k = 0; k < 16; k++) {
            const float* wrow = Wsm + (kc * 16 + k) * WPAD;
            ulonglong2 wA = *reinterpret_cast<const ulonglong2*>(wrow + cx * 8);
            ulonglong2 wB = *reinterpret_cast<const ulonglong2*>(wrow + cx * 8 + 4);
            const float* xrowp = Xsm + (buf * 16 + k) * WPAD;
            float4 x0 = *reinterpret_cast<const float4*>(xrowp + ry * 8);
            float4 x1 = *reinterpret_cast<const float4*>(xrowp + ry * 8 + 4);
            float xr[8] = {x0.x, x0.y, x0.z, x0.w, x1.x, x1.y, x1.z, x1.w};
#pragma unroll
            for (int a = 0; a < 8; a++) {
                uint64_t xd;
                PACK2(xd, xr[a], xr[a]);
                FMA2(acc[a][0], xd, wA.x);
                FMA2(acc[a][1], xd, wA.y);
                FMA2(acc[a][2], xd, wB.x);
                FMA2(acc[a][3], xd, wB.y);
            }
        }
        if (kc < 7) {
            stage_x(buf ^ 1, px0, px1, pu);
            __syncthreads();
        }
    }

    // epilogue: f32x2 pairs -> bf16x2, 16B per row per thread
#pragma unroll
    for (int a = 0; a < 8; a++) {
        int r = row0 + ry * 8 + a;
        if (r < n) {
            uint4 o;
            float lo, hi;
            UNPACK2(lo, hi, acc[a][0]); CVT_BF2(o.x, lo, hi);
            UNPACK2(lo, hi, acc[a][1]); CVT_BF2(o.y, lo, hi);
            UNPACK2(lo, hi, acc[a][2]); CVT_BF2(o.z, lo, hi);
            UNPACK2(lo, hi, acc[a][3]); CVT_BF2(o.w, lo, hi);
            *reinterpret_cast<uint4*>(&g_hb[(size_t)r * 64 + cx * 4]) = o;
        }
    }
}

// ================= fused aggregate + relu; act-store OR pool =================
__global__ void gather_kernel(const float* __restrict__ bias,
                              const int* __restrict__ batch, int do_pool) {
    int w = (blockIdx.x * blockDim.x + threadIdx.x) >> 5;
    int lane = threadIdx.x & 31;
    if (w >= NN) return;

    const uint2* __restrict__ hb = reinterpret_cast<const uint2*>(g_hb);
    int start = g_ptr[w];
    int end   = g_ptr[w + 1];
    float di = g_dinv[w];
    float s = di * di;

    uint2 us = hb[(size_t)w * 32 + lane];
    float2 s0 = bf2f(us.x), s1 = bf2f(us.y);
    float4 bv = reinterpret_cast<const float4*>(bias)[lane];
    float4 acc;
    acc.x = s0.x * s + bv.x;
    acc.y = s0.y * s + bv.y;
    acc.z = s1.x * s + bv.z;
    acc.w = s1.y * s + bv.w;

    int e = start;
    for (; e + 8 <= end; e += 8) {
        int   ri[8];
        float ni[8];
#pragma unroll
        for (int j = 0; j < 8; j++) { ri[j] = g_csr_row[e + j]; ni[j] = g_csr_norm[e + j]; }
        uint2 v[8];
#pragma unroll
        for (int j = 0; j < 8; j++) v[j] = hb[(size_t)ri[j] * 32 + lane];
#pragma unroll
        for (int j = 0; j < 8; j++) {
            float2 p0 = bf2f(v[j].x), p1 = bf2f(v[j].y);
            acc.x += ni[j] * p0.x;
            acc.y += ni[j] * p0.y;
            acc.z += ni[j] * p1.x;
            acc.w += ni[j] * p1.y;
        }
    }
    if (e + 4 <= end) {
        int   r0 = g_csr_row[e],   r1 = g_csr_row[e+1];
        int   r2 = g_csr_row[e+2], r3 = g_csr_row[e+3];
        float n0 = g_csr_norm[e],   n1 = g_csr_norm[e+1];
        float n2 = g_csr_norm[e+2], n3 = g_csr_norm[e+3];
        uint2 v0 = hb[(size_t)r0 * 32 + lane];
        uint2 v1 = hb[(size_t)r1 * 32 + lane];
        uint2 v2 = hb[(size_t)r2 * 32 + lane];
        uint2 v3 = hb[(size_t)r3 * 32 + lane];
        float2 a0 = bf2f(v0.x), b0 = bf2f(v0.y);
        float2 a1 = bf2f(v1.x), b1 = bf2f(v1.y);
        float2 a2 = bf2f(v2.x), b2 = bf2f(v2.y);
        float2 a3 = bf2f(v3.x), b3 = bf2f(v3.y);
        acc.x += n0*a0.x + n1*a1.x + n2*a2.x + n3*a3.x;
        acc.y += n0*a0.y + n1*a1.y + n2*a2.y + n3*a3.y;
        acc.z += n0*b0.x + n1*b1.x + n2*b2.x + n3*b3.x;
        acc.w += n0*b0.y + n1*b1.y + n2*b2.y + n3*b3.y;
        e += 4;
    }
    for (; e < end; e++) {
        int   r0 = g_csr_row[e];
        float n0 = g_csr_norm[e];
        uint2 v0 = hb[(size_t)r0 * 32 + lane];
        float2 p0 = bf2f(v0.x), p1 = bf2f(v0.y);
        acc.x += n0*p0.x; acc.y += n0*p0.y;
        acc.z += n0*p1.x; acc.w += n0*p1.y;
    }

    acc.x = fmaxf(acc.x, 0.f); acc.y = fmaxf(acc.y, 0.f);
    acc.z = fmaxf(acc.z, 0.f); acc.w = fmaxf(acc.w, 0.f);

    if (do_pool) {
        // layer 2: activations feed only the mean-pool — no act store
        int g = batch[w];
        if (g < 0) g = 0;
        if (g >= NG) g = NG - 1;
        float* dst = &g_pool[g * F + lane * 4];
        atomicAdd(dst + 0, acc.x);
        atomicAdd(dst + 1, acc.y);
        atomicAdd(dst + 2, acc.z);
        atomicAdd(dst + 3, acc.w);
    } else {
        // layer 1: store bf16 activations for gemm2
        uint2 o;
        CVT_BF2(o.x, acc.x, acc.y);
        CVT_BF2(o.y, acc.z, acc.w);
        reinterpret_cast<uint2*>(g_actb)[(size_t)w * 32 + lane] = o;
    }
}

// ================= head MLP =================
__global__ void head_kernel(const float* __restrict__ l1w, const float* __restrict__ l1b,
                            const float* __restrict__ l2w, const float* __restrict__ l2b,
                            float* __restrict__ out) {
    int g = blockIdx.x;
    int t = threadIdx.x;
    __shared__ float gv[F];
    __shared__ float hv[F];
    __shared__ float red[F];

    float c = fmaxf(g_cnt[g], 1.0f);
    gv[t] = g_pool[g * F + t] / c;
    __syncthreads();

    float s = l1b[t];
    const float* wrow = l1w + t * F;
#pragma unroll 8
    for (int k = 0; k < F; k++) s += wrow[k] * gv[k];
    hv[t] = fmaxf(s, 0.f);
    __syncthreads();

    for (int o = 0; o < 2; o++) {
        red[t] = l2w[o * F + t] * hv[t];
        __syncthreads();
        for (int st = 64; st > 0; st >>= 1) {
            if (t < st) red[t] += red[t + st];
            __syncthreads();
        }
        if (t == 0) out[g * 2 + o] = red[0] + l2b[o];
        __syncthreads();
    }
}

extern "C" void kernel_launch(void* const* d_in, const int* in_sizes, int n_in,
                              void* d_out, int out_size) {
    const float* x     = (const float*)d_in[0];
    const int*   ei    = (const int*)d_in[1];
    const float* ew    = (const float*)d_in[2];
    const int*   batch = (const int*)d_in[3];
    const float* W1    = (const float*)d_in[4];
    const float* b1    = (const float*)d_in[5];
    const float* W2    = (const float*)d_in[6];
    const float* b2    = (const float*)d_in[7];
    const float* l1w   = (const float*)d_in[8];
    const float* l1b   = (const float*)d_in[9];
    const float* l2w   = (const float*)d_in[10];
    const float* l2b   = (const float*)d_in[11];
    float* out         = (float*)d_out;

    // lazily-created side stream + events (host objects only; no device memory)
    static cudaStream_t s2 = nullptr;
    static cudaEvent_t ev_fork = nullptr, ev_gemm = nullptr;
    static int smem_set = 0;
    if (s2 == nullptr) {
        cudaStreamCreateWithFlags(&s2, cudaStreamNonBlocking);
        cudaEventCreateWithFlags(&ev_fork, cudaEventDisableTiming);
        cudaEventCreateWithFlags(&ev_gemm, cudaEventDisableTiming);
    }
    if (!smem_set) {
        cudaFuncSetAttribute(gemm128_kernel<0>,
                             cudaFuncAttributeMaxDynamicSharedMemorySize, SM_GEMM_BYTES);
        cudaFuncSetAttribute(gemm128_kernel<1>,
                             cudaFuncAttributeMaxDynamicSharedMemorySize, SM_GEMM_BYTES);
        smem_set = 1;
    }

    const int T = 256;
    int gemm_blocks   = (NN + 127) / 128;
    int gather_blocks = (NN * 32 + T - 1) / T;

    // fork point: side stream joins the capture graph here
    cudaEventRecord(ev_fork, 0);
    cudaStreamWaitEvent(s2, ev_fork, 0);

    // branch A (main): CSR build
    zero_misc_kernel<<<(NN + T - 1) / T, T>>>();
    deg_count_kernel<<<(NE / 2 + T - 1) / T, T>>>(ei, ew);
    dinv_kernel<<<(NN + T - 1) / T, T>>>(batch);

    // branch B (s2): GEMM layer 1 (4th launch -> ncu window)
    gemm128_kernel<0><<<gemm_blocks, T, SM_GEMM_BYTES, s2>>>(x, W1, NN);
    cudaEventRecord(ev_gemm, s2);

    // branch A continued: parallel 3-kernel scan + fill
    scan1_kernel<<<NSB, SCAN_B>>>();
    scan2_kernel<<<1, 32>>>();
    scan3_kernel<<<(NN + T - 1) / T, T>>>();
    fill_kernel<<<(NE + T - 1) / T, T>>>(ei, ew);

    // join: gather1 needs CSR (A) AND g_hb from gemm1 (B)
    cudaStreamWaitEvent(0, ev_gemm, 0);
    gather_kernel<<<gather_blocks, T>>>(b1, batch, 0);

    // layer 2 (+ fused mean-pool accumulation, no act store)
    gemm128_kernel<1><<<gemm_blocks, T, SM_GEMM_BYTES>>>(x, W2, NN);
    gather_kernel<<<gather_blocks, T>>>(b2, batch, 1);

    // head
    head_kernel<<<NG, F>>>(l1w, l1b, l2w, l2b, out);
}

// round 16
// speedup vs baseline: 1.9129x; 1.4591x over previous
#include <cuda_runtime.h>
#include <cuda_bf16.h>
#include <cstdint>

#define NN 50000
#define NE 800000
#define F  128
#define NG 100
#define SCAN_B 1024
#define NSB ((NN + SCAN_B - 1) / SCAN_B)   // 49

// ---- scratch (static __device__ globals; no allocation anywhere) ----
__device__ __align__(16) float g_deg[NN];
__device__ __align__(16) float g_dinv[NN];
__device__ __align__(16) uint32_t g_hb[NN * 64];    // XW product, bf16x2 (128 bf16/row)
__device__ __align__(16) uint32_t g_actb[NN * 64];  // relu activations, bf16x2
__device__ __align__(16) float g_pool[NG * F];
__device__ __align__(16) float g_cnt[NG];
__device__ int   g_cnt_in[NN];
__device__ int   g_incl[NN];
__device__ int   g_bsum[NSB];
__device__ int   g_ptr[NN + 1];
__device__ int   g_cur[NN];
__device__ __align__(16) int   g_csr_row[NE];
__device__ __align__(16) float g_csr_norm[NE];

// packed f32x2 helpers (B300 FFMA2 — only reachable via PTX)
#define FMA2(d, a, b) \
    asm("fma.rn.f32x2 %0, %1, %2, %0;" : "+l"(d) : "l"(a), "l"(b))
#define PACK2(out, lo, hi) \
    asm("mov.b64 %0, {%1, %2};" : "=l"(out) : "f"(lo), "f"(hi))
#define UNPACK2(lo, hi, in) \
    asm("mov.b64 {%0, %1}, %2;" : "=f"(lo), "=f"(hi) : "l"(in))
// d = bf16x2 with lo=a, hi=b
#define CVT_BF2(d, a, b) \
    asm("cvt.rn.bf16x2.f32 %0, %1, %2;" : "=r"(d) : "f"(b), "f"(a))

__device__ __forceinline__ float2 bf2f(uint32_t u) {
    return __bfloat1622float2(*reinterpret_cast<__nv_bfloat162*>(&u));
}

// ================= CSR build =================
__global__ void zero_misc_kernel() {
    int i = blockIdx.x * blockDim.x + threadIdx.x;
    if (i < NN) { g_deg[i] = 0.f; g_cnt_in[i] = 0; }
    if (i < NG * F) g_pool[i] = 0.f;
    if (i < NG) g_cnt[i] = 0.f;
}

__global__ void deg_count_kernel(const int* __restrict__ ei,
                                 const float* __restrict__ ew) {
    int t = blockIdx.x * blockDim.x + threadIdx.x;
    int e = t * 2;
    if (e < NE) {
        int2   c2 = *reinterpret_cast<const int2*>(&ei[NE + e]);
        float2 w2 = *reinterpret_cast<const float2*>(&ew[e]);
        atomicAdd(&g_deg[c2.x], w2.x);
        atomicAdd(&g_cnt_in[c2.x], 1);
        atomicAdd(&g_deg[c2.y], w2.y);
        atomicAdd(&g_cnt_in[c2.y], 1);
    }
}

// per-block inclusive scan of counts + fused dinv / graph-count work
__global__ void scan1_kernel(const int* __restrict__ batch) {
    __shared__ int s[SCAN_B];
    int tid = threadIdx.x;
    int i = blockIdx.x * SCAN_B + tid;
    int v = (i < NN) ? g_cnt_in[i] : 0;
    if (i < NN) {
        g_dinv[i] = rsqrtf(g_deg[i] + 1.0f);
        int g = batch[i];
        if (g < 0) g = 0;
        if (g >= NG) g = NG - 1;
        atomicAdd(&g_cnt[g], 1.0f);
    }
    s[tid] = v;
    __syncthreads();
#pragma unroll
    for (int off = 1; off < SCAN_B; off <<= 1) {
        int t = (tid >= off) ? s[tid - off] : 0;
        __syncthreads();
        s[tid] += t;
        __syncthreads();
    }
    if (i < NN) g_incl[i] = s[tid];
    if (tid == SCAN_B - 1) g_bsum[blockIdx.x] = s[tid];
}

// combine: each CTA locally scans the 49 block sums (smem), then finalizes ptr/cur
__global__ void scan3_kernel() {
    __shared__ int spre[NSB];
    int t = threadIdx.x;
    if (t < NSB) spre[t] = g_bsum[t];
    __syncthreads();
    if (t == 0) {
        int run = 0;
#pragma unroll 7
        for (int b = 0; b < NSB; b++) { int v = spre[b]; spre[b] = run; run += v; }
    }
    __syncthreads();
    int i = blockIdx.x * blockDim.x + t;
    if (i < NN) {
        int tt = g_incl[i] + spre[i >> 10];
        g_ptr[i + 1] = tt;
        g_cur[i] = tt - g_cnt_in[i];
        if (i == 0) g_ptr[0] = 0;
    }
}

__global__ void fill_kernel(const int* __restrict__ ei,
                            const float* __restrict__ ew) {
    int e = blockIdx.x * blockDim.x + threadIdx.x;
    if (e < NE) {
        int r = ei[e];
        int c = ei[NE + e];
        int pos = atomicAdd(&g_cur[c], 1);
        g_csr_row[pos] = r;
        g_csr_norm[pos] = g_dinv[r] * ew[e] * g_dinv[c];
    }
}

// ================= W-resident pipelined FFMA2 GEMM -> bf16 table =================
// USE_ACT=0: X from fp32 Xext. USE_ACT=1: X from bf16 g_actb.
#define WPAD 136
#define SM_W_FLOATS (128 * WPAD)
#define SM_X_FLOATS (2 * 16 * WPAD)
#define SM_GEMM_BYTES ((SM_W_FLOATS + SM_X_FLOATS) * 4)  // 87040

template <int USE_ACT>
__global__ void __launch_bounds__(256, 2)
gemm128_kernel(const float* __restrict__ Xext, const float* __restrict__ W, int n) {
    extern __shared__ __align__(16) float sm[];
    float* Wsm = sm;                    // [128][WPAD]
    float* Xsm = sm + SM_W_FLOATS;      // [2][16][WPAD]

    int tid = threadIdx.x;
    int cx = tid & 15;
    int ry = tid >> 4;
    int row0 = blockIdx.x * 128;

    int lr   = tid >> 1;
    int half = tid & 1;
    int kb   = half * 8;

    int xrow = row0 + lr;
    bool ok = xrow < n;
    int srow = ok ? xrow : 0;
    const float*    Xp  = Xext + (size_t)srow * 128 + kb;
    const uint32_t* Xbp = g_actb + (size_t)srow * 64 + kb / 2;
    const float*    Wp  = W + lr * 128 + kb;

#pragma unroll
    for (int kc = 0; kc < 8; kc++) {
        float4 w0 = *reinterpret_cast<const float4*>(Wp + kc * 16);
        float4 w1 = *reinterpret_cast<const float4*>(Wp + kc * 16 + 4);
        float* dst = Wsm + (kc * 16 + kb) * WPAD + lr;
        dst[0 * WPAD] = w0.x; dst[1 * WPAD] = w0.y;
        dst[2 * WPAD] = w0.z; dst[3 * WPAD] = w0.w;
        dst[4 * WPAD] = w1.x; dst[5 * WPAD] = w1.y;
        dst[6 * WPAD] = w1.z; dst[7 * WPAD] = w1.w;
    }

    auto stage_x = [&](int b, const float4& a0, const float4& a1, const uint4& u) {
        float v[8];
        if (USE_ACT) {
            float2 f0 = bf2f(u.x), f1 = bf2f(u.y), f2 = bf2f(u.z), f3 = bf2f(u.w);
            v[0] = f0.x; v[1] = f0.y; v[2] = f1.x; v[3] = f1.y;
            v[4] = f2.x; v[5] = f2.y; v[6] = f3.x; v[7] = f3.y;
        } else {
            v[0] = a0.x; v[1] = a0.y; v[2] = a0.z; v[3] = a0.w;
            v[4] = a1.x; v[5] = a1.y; v[6] = a1.z; v[7] = a1.w;
        }
        float* dst = Xsm + (b * 16 + kb) * WPAD + lr;
#pragma unroll
        for (int j = 0; j < 8; j++) dst[j * WPAD] = ok ? v[j] : 0.f;
    };

    {
        float4 a0 = make_float4(0.f,0.f,0.f,0.f), a1 = a0;
        uint4 u = make_uint4(0,0,0,0);
        if (USE_ACT) u = *reinterpret_cast<const uint4*>(Xbp);
        else { a0 = *reinterpret_cast<const float4*>(Xp);
               a1 = *reinterpret_cast<const float4*>(Xp + 4); }
        stage_x(0, a0, a1, u);
    }
    __syncthreads();

    uint64_t acc[8][4];
#pragma unroll
    for (int a = 0; a < 8; a++)
#pragma unroll
        for (int b = 0; b < 4; b++) acc[a][b] = 0ull;

    float4 px0, px1; uint4 pu;
#pragma unroll
    for (int kc = 0; kc < 8; kc++) {
        int buf = kc & 1;
        if (kc < 7) {
            if (USE_ACT) pu = *reinterpret_cast<const uint4*>(Xbp + (kc + 1) * 8);
            else {
                px0 = *reinterpret_cast<const float4*>(Xp + (kc + 1) * 16);
                px1 = *reinterpret_cast<const float4*>(Xp + (kc + 1) * 16 + 4);
            }
        }

#pragma unroll
        for (int k = 0; k < 16; k++) {
            const float* wrow = Wsm + (kc * 16 + k) * WPAD;
            ulonglong2 wA = *reinterpret_cast<const ulonglong2*>(wrow + cx * 8);
            ulonglong2 wB = *reinterpret_cast<const ulonglong2*>(wrow + cx * 8 + 4);
            const float* xrowp = Xsm + (buf * 16 + k) * WPAD;
            float4 x0 = *reinterpret_cast<const float4*>(xrowp + ry * 8);
            float4 x1 = *reinterpret_cast<const float4*>(xrowp + ry * 8 + 4);
            float xr[8] = {x0.x, x0.y, x0.z, x0.w, x1.x, x1.y, x1.z, x1.w};
#pragma unroll
            for (int a = 0; a < 8; a++) {
                uint64_t xd;
                PACK2(xd, xr[a], xr[a]);
                FMA2(acc[a][0], xd, wA.x);
                FMA2(acc[a][1], xd, wA.y);
                FMA2(acc[a][2], xd, wB.x);
                FMA2(acc[a][3], xd, wB.y);
            }
        }
        if (kc < 7) {
            stage_x(buf ^ 1, px0, px1, pu);
            __syncthreads();
        }
    }

#pragma unroll
    for (int a = 0; a < 8; a++) {
        int r = row0 + ry * 8 + a;
        if (r < n) {
            uint4 o;
            float lo, hi;
            UNPACK2(lo, hi, acc[a][0]); CVT_BF2(o.x, lo, hi);
            UNPACK2(lo, hi, acc[a][1]); CVT_BF2(o.y, lo, hi);
            UNPACK2(lo, hi, acc[a][2]); CVT_BF2(o.z, lo, hi);
            UNPACK2(lo, hi, acc[a][3]); CVT_BF2(o.w, lo, hi);
            *reinterpret_cast<uint4*>(&g_hb[(size_t)r * 64 + cx * 4]) = o;
        }
    }
}

// ================= fused aggregate + relu; act-store OR block-privatized pool =================
__global__ void gather_kernel(const float* __restrict__ bias,
                              const int* __restrict__ batch, int do_pool) {
    __shared__ float sacc[8][128];
    __shared__ int sgid[8];

    int gw = (blockIdx.x * blockDim.x + threadIdx.x) >> 5;
    int lane = threadIdx.x & 31;
    int wid = threadIdx.x >> 5;
    bool valid = gw < NN;
    int w = valid ? gw : NN - 1;   // clamped safe index (writes guarded)

    const uint2* __restrict__ hb = reinterpret_cast<const uint2*>(g_hb);
    int start = g_ptr[w];
    int end   = g_ptr[w + 1];
    float di = g_dinv[w];
    float s = di * di;

    uint2 us = hb[(size_t)w * 32 + lane];
    float2 s0 = bf2f(us.x), s1 = bf2f(us.y);
    float4 bv = reinterpret_cast<const float4*>(bias)[lane];
    float4 acc;
    acc.x = s0.x * s + bv.x;
    acc.y = s0.y * s + bv.y;
    acc.z = s1.x * s + bv.z;
    acc.w = s1.y * s + bv.w;

    int e = start;
    for (; e + 8 <= end; e += 8) {
        int   ri[8];
        float ni[8];
#pragma unroll
        for (int j = 0; j < 8; j++) { ri[j] = g_csr_row[e + j]; ni[j] = g_csr_norm[e + j]; }
        uint2 v[8];
#pragma unroll
        for (int j = 0; j < 8; j++) v[j] = hb[(size_t)ri[j] * 32 + lane];
#pragma unroll
        for (int j = 0; j < 8; j++) {
            float2 p0 = bf2f(v[j].x), p1 = bf2f(v[j].y);
            acc.x += ni[j] * p0.x;
            acc.y += ni[j] * p0.y;
            acc.z += ni[j] * p1.x;
            acc.w += ni[j] * p1.y;
        }
    }
    if (e + 4 <= end) {
        int   r0 = g_csr_row[e],   r1 = g_csr_row[e+1];
        int   r2 = g_csr_row[e+2], r3 = g_csr_row[e+3];
        float n0 = g_csr_norm[e],   n1 = g_csr_norm[e+1];
        float n2 = g_csr_norm[e+2], n3 = g_csr_norm[e+3];
        uint2 v0 = hb[(size_t)r0 * 32 + lane];
        uint2 v1 = hb[(size_t)r1 * 32 + lane];
        uint2 v2 = hb[(size_t)r2 * 32 + lane];
        uint2 v3 = hb[(size_t)r3 * 32 + lane];
        float2 a0 = bf2f(v0.x), b0 = bf2f(v0.y);
        float2 a1 = bf2f(v1.x), b1 = bf2f(v1.y);
        float2 a2 = bf2f(v2.x), b2 = bf2f(v2.y);
        float2 a3 = bf2f(v3.x), b3 = bf2f(v3.y);
        acc.x += n0*a0.x + n1*a1.x + n2*a2.x + n3*a3.x;
        acc.y += n0*a0.y + n1*a1.y + n2*a2.y + n3*a3.y;
        acc.z += n0*b0.x + n1*b1.x + n2*b2.x + n3*b3.x;
        acc.w += n0*b0.y + n1*b1.y + n2*b2.y + n3*b3.y;
        e += 4;
    }
    for (; e < end; e++) {
        int   r0 = g_csr_row[e];
        float n0 = g_csr_norm[e];
        uint2 v0 = hb[(size_t)r0 * 32 + lane];
        float2 p0 = bf2f(v0.x), p1 = bf2f(v0.y);
        acc.x += n0*p0.x; acc.y += n0*p0.y;
        acc.z += n0*p1.x; acc.w += n0*p1.y;
    }

    acc.x = fmaxf(acc.x, 0.f); acc.y = fmaxf(acc.y, 0.f);
    acc.z = fmaxf(acc.z, 0.f); acc.w = fmaxf(acc.w, 0.f);

    if (!do_pool) {
        // layer 1: store bf16 activations for gemm2
        if (valid) {
            uint2 o;
            CVT_BF2(o.x, acc.x, acc.y);
            CVT_BF2(o.y, acc.z, acc.w);
            reinterpret_cast<uint2*>(g_actb)[(size_t)w * 32 + lane] = o;
        }
        return;
    }

    // layer 2: block-privatized mean-pool accumulation (batch is sorted)
    int g = -1;
    if (valid) {
        g = batch[w];
        if (g < 0) g = 0;
        if (g >= NG) g = NG - 1;
    }
    if (lane == 0) sgid[wid] = g;
    *reinterpret_cast<float4*>(&sacc[wid][lane * 4]) = acc;
    __syncthreads();

    if (threadIdx.x < 128) {
        int f = threadIdx.x;
        float run = 0.f;
        int cur = sgid[0];
#pragma unroll
        for (int j = 0; j < 8; j++) {
            int gj = sgid[j];
            float v = sacc[j][f];
            if (gj != cur) {
                if (cur >= 0) atomicAdd(&g_pool[cur * F + f], run);
                run = 0.f;
                cur = gj;
            }
            run += v;
        }
        if (cur >= 0) atomicAdd(&g_pool[cur * F + f], run);
    }
}

// ================= head MLP =================
__global__ void head_kernel(const float* __restrict__ l1w, const float* __restrict__ l1b,
                            const float* __restrict__ l2w, const float* __restrict__ l2b,
                            float* __restrict__ out) {
    int g = blockIdx.x;
    int t = threadIdx.x;
    __shared__ float gv[F];
    __shared__ float hv[F];
    __shared__ float red[F];

    float c = fmaxf(g_cnt[g], 1.0f);
    gv[t] = g_pool[g * F + t] / c;
    __syncthreads();

    float s = l1b[t];
    const float* wrow = l1w + t * F;
#pragma unroll 8
    for (int k = 0; k < F; k++) s += wrow[k] * gv[k];
    hv[t] = fmaxf(s, 0.f);
    __syncthreads();

    for (int o = 0; o < 2; o++) {
        red[t] = l2w[o * F + t] * hv[t];
        __syncthreads();
        for (int st = 64; st > 0; st >>= 1) {
            if (t < st) red[t] += red[t + st];
            __syncthreads();
        }
        if (t == 0) out[g * 2 + o] = red[0] + l2b[o];
        __syncthreads();
    }
}

extern "C" void kernel_launch(void* const* d_in, const int* in_sizes, int n_in,
                              void* d_out, int out_size) {
    const float* x     = (const float*)d_in[0];
    const int*   ei    = (const int*)d_in[1];
    const float* ew    = (const float*)d_in[2];
    const int*   batch = (const int*)d_in[3];
    const float* W1    = (const float*)d_in[4];
    const float* b1    = (const float*)d_in[5];
    const float* W2    = (const float*)d_in[6];
    const float* b2    = (const float*)d_in[7];
    const float* l1w   = (const float*)d_in[8];
    const float* l1b   = (const float*)d_in[9];
    const float* l2w   = (const float*)d_in[10];
    const float* l2b   = (const float*)d_in[11];
    float* out         = (float*)d_out;

    // lazily-created side stream + events (host objects only; no device memory)
    static cudaStream_t s2 = nullptr;
    static cudaEvent_t ev_fork = nullptr, ev_gemm = nullptr;
    static int smem_set = 0;
    if (s2 == nullptr) {
        cudaStreamCreateWithFlags(&s2, cudaStreamNonBlocking);
        cudaEventCreateWithFlags(&ev_fork, cudaEventDisableTiming);
        cudaEventCreateWithFlags(&ev_gemm, cudaEventDisableTiming);
    }
    if (!smem_set) {
        cudaFuncSetAttribute(gemm128_kernel<0>,
                             cudaFuncAttributeMaxDynamicSharedMemorySize, SM_GEMM_BYTES);
        cudaFuncSetAttribute(gemm128_kernel<1>,
                             cudaFuncAttributeMaxDynamicSharedMemorySize, SM_GEMM_BYTES);
        smem_set = 1;
    }

    const int T = 256;
    int gemm_blocks   = (NN + 127) / 128;
    int gather_blocks = (NN * 32 + T - 1) / T;

    // fork point: side stream joins the capture graph here
    cudaEventRecord(ev_fork, 0);
    cudaStreamWaitEvent(s2, ev_fork, 0);

    // branch A (main): CSR build; launches 1..3
    zero_misc_kernel<<<(NN + T - 1) / T, T>>>();
    deg_count_kernel<<<(NE / 2 + T - 1) / T, T>>>(ei, ew);
    scan1_kernel<<<NSB, SCAN_B>>>(batch);   // scan + dinv + graph counts

    // branch B (s2): GEMM layer 1 (4th launch -> ncu window)
    gemm128_kernel<0><<<gemm_blocks, T, SM_GEMM_BYTES, s2>>>(x, W1, NN);
    cudaEventRecord(ev_gemm, s2);

    // branch A continued: finalize ptr/cur (with local bsum scan) + fill
    scan3_kernel<<<(NN + T - 1) / T, T>>>();
    fill_kernel<<<(NE + T - 1) / T, T>>>(ei, ew);

    // join: gather1 needs CSR (A) AND g_hb from gemm1 (B)
    cudaStreamWaitEvent(0, ev_gemm, 0);
    gather_kernel<<<gather_blocks, T>>>(b1, batch, 0);

    // layer 2 (+ privatized mean-pool accumulation, no act store)
    gemm128_kernel<1><<<gemm_blocks, T, SM_GEMM_BYTES>>>(x, W2, NN);
    gather_kernel<<<gather_blocks, T>>>(b2, batch, 1);

    // head
    head_kernel<<<NG, F>>>(l1w, l1b, l2w, l2b, out);
}